// round 8
// baseline (speedup 1.0000x reference)
#include <cuda_runtime.h>
#include <math.h>

#define NN 100000
#define EE 1250000
#define DD 64

// ---------------- scratch (device globals) ----------------
__device__ float    g_x   [NN*DD];
__device__ float    g_xt  [NN*DD];
__device__ float    g_h   [NN*DD];
__device__ float    g_xd  [NN*6*DD];      // x_dense [N,384]
__device__ int      g_cnt [NN];
__device__ int      g_fill[NN];
__device__ int      g_start[NN];
__device__ unsigned g_elist[EE];          // src | signbit<<31
__device__ int      g_bsum[1024];
__device__ float    g_part[1480*128];     // per-block column stat partials
__device__ float    g_gn  [256];

__device__ __forceinline__ float gelu_f(float v) {
    return 0.5f * v * (1.0f + erff(v * 0.70710678118654752440f));
}

// packed fp32x2 helpers (sm_100+)
__device__ __forceinline__ void ffma2(unsigned long long& d, unsigned long long a,
                                      unsigned long long b) {
    asm("fma.rn.f32x2 %0, %1, %2, %0;" : "+l"(d) : "l"(a), "l"(b));
}
__device__ __forceinline__ float2 unpk(unsigned long long v) {
    float2 f;
    asm("mov.b64 {%0, %1}, %2;" : "=f"(f.x), "=f"(f.y) : "l"(v));
    return f;
}
__device__ __forceinline__ unsigned long long dup2(float x) {
    unsigned long long r;
    asm("mov.b64 %0, {%1, %1};" : "=l"(r) : "f"(x));
    return r;
}
union F4U { float4 f; unsigned long long u[2]; };

// cp.async helpers
__device__ __forceinline__ unsigned smem_u32(const void* p) {
    return (unsigned)__cvta_generic_to_shared(p);
}
__device__ __forceinline__ void cpasync16(unsigned dst, const void* src) {
    asm volatile("cp.async.cg.shared.global [%0], [%1], 16;" :: "r"(dst), "l"(src));
}
#define CP_COMMIT() asm volatile("cp.async.commit_group;" ::: "memory")
#define CP_WAIT1()  asm volatile("cp.async.wait_group 1;" ::: "memory")

// ---------------- utility ----------------
__global__ void zero_all_kernel(int* cnt, int* fill) {
    int i = blockIdx.x * blockDim.x + threadIdx.x;
    if (i < NN) { cnt[i] = 0; fill[i] = 0; }
}

// ---------------- CSR build ----------------
__global__ void count_kernel(const int* __restrict__ ei, int* __restrict__ cnt) {
    int e = blockIdx.x * blockDim.x + threadIdx.x;
    if (e < EE) atomicAdd(&cnt[ei[e*3 + 1]], 1);
}

#define SCAN_BS 1024
__global__ void scan_block_kernel(const int* __restrict__ cnt, int* __restrict__ excl,
                                  int* __restrict__ bsum, int n) {
    __shared__ int s[SCAN_BS];
    int i = blockIdx.x * SCAN_BS + threadIdx.x;
    int v = (i < n) ? cnt[i] : 0;
    s[threadIdx.x] = v;
    __syncthreads();
    for (int off = 1; off < SCAN_BS; off <<= 1) {
        int t = (threadIdx.x >= off) ? s[threadIdx.x - off] : 0;
        __syncthreads();
        s[threadIdx.x] += t;
        __syncthreads();
    }
    if (i < n) excl[i] = s[threadIdx.x] - v;
    if (threadIdx.x == SCAN_BS - 1) bsum[blockIdx.x] = s[SCAN_BS - 1];
}
__global__ void scan_part_kernel(int* __restrict__ bs, int nb) {
    __shared__ int s[SCAN_BS];
    int v = (threadIdx.x < nb) ? bs[threadIdx.x] : 0;
    s[threadIdx.x] = v;
    __syncthreads();
    for (int off = 1; off < SCAN_BS; off <<= 1) {
        int t = (threadIdx.x >= off) ? s[threadIdx.x - off] : 0;
        __syncthreads();
        s[threadIdx.x] += t;
        __syncthreads();
    }
    if (threadIdx.x < nb) bs[threadIdx.x] = s[threadIdx.x] - v;
}
__global__ void scan_add_kernel(int* __restrict__ excl, const int* __restrict__ bs, int n) {
    int i = blockIdx.x * SCAN_BS + threadIdx.x;
    if (i < n) excl[i] += bs[blockIdx.x];
}
__global__ void fill_kernel(const int* __restrict__ ei, const int* __restrict__ start,
                            int* __restrict__ fill, unsigned* __restrict__ elist) {
    int e = blockIdx.x * blockDim.x + threadIdx.x;
    if (e >= EE) return;
    int src = ei[e*3 + 0];
    int dst = ei[e*3 + 1];
    int sg  = ei[e*3 + 2];
    int pos = start[dst] + atomicAdd(&fill[dst], 1);
    elist[pos] = (unsigned)src | (sg < 0 ? 0x80000000u : 0u);
}

// ---------------- persistent GEMM infrastructure -------------------
#define TILE_ROWS 64
#define SX_LD 68
#define CHUNK_F (64*SX_LD)
#define P_GRID 444

__device__ __forceinline__ void gemm_load_w(const float* __restrict__ W, float* sWt,
                                            int t, int nthreads) {
    const float4* W4 = (const float4*)W;
    for (int v = t; v < 1024; v += nthreads) {
        int k = v >> 4, j4 = v & 15;
        float4 w = W4[k*16 + j4];
        sWt[(j4*4+0)*SX_LD + k] = w.x;
        sWt[(j4*4+1)*SX_LD + k] = w.y;
        sWt[(j4*4+2)*SX_LD + k] = w.z;
        sWt[(j4*4+3)*SX_LD + k] = w.w;
    }
}

__device__ __forceinline__ void prefetch_x(const float* __restrict__ in, int in_ld, int kc,
                                           int rowBase, int rows, int nrows, float* buf,
                                           int t, int nthreads) {
    for (int v = t; v < rows*16; v += nthreads) {
        int r = v >> 4, c4 = v & 15;
        int gr = rowBase + r;
        if (gr >= nrows) gr = nrows - 1;
        cpasync16(smem_u32(buf + r*SX_LD + c4*4), in + (size_t)gr*in_ld + kc + c4*4);
    }
}

__device__ __forceinline__ void gemm_mm(const float* sX, const float* sWt,
                                        unsigned long long acc[4][4], int colg, int rowg) {
#pragma unroll
    for (int k4 = 0; k4 < 16; k4++) {
        F4U wv[4];
#pragma unroll
        for (int i = 0; i < 4; i++)
            wv[i].f = *(const float4*)(sWt + (colg + 16*i)*SX_LD + k4*4);
#pragma unroll
        for (int r = 0; r < 4; r++) {
            F4U xv;
            xv.f = *(const float4*)(sX + (rowg*4 + r)*SX_LD + k4*4);
#pragma unroll
            for (int i = 0; i < 4; i++) {
                ffma2(acc[r][i], xv.u[0], wv[i].u[0]);
                ffma2(acc[r][i], xv.u[1], wv[i].u[1]);
            }
        }
    }
}

// ---- persistent K=64 GEMM: out = in @ W + b ----
__global__ __launch_bounds__(256, 3)
void gemm64_p(const float* __restrict__ in, int in_ld,
              const float* __restrict__ W, const float* __restrict__ bias,
              float* __restrict__ out, int nrows, int ntiles)
{
    extern __shared__ float sm[];
    float* sX0 = sm;
    float* sX1 = sm + CHUNK_F;
    float* sWt = sm + 2*CHUNK_F;
    int t = threadIdx.x;
    int colg = t & 15, rowg = t >> 4;

    gemm_load_w(W, sWt, t, 256);

    float bv[4];
#pragma unroll
    for (int i = 0; i < 4; i++) bv[i] = bias[colg + 16*i];

    prefetch_x(in, in_ld, 0, blockIdx.x*TILE_ROWS, 64, nrows, sX0, t, 256);
    CP_COMMIT();

    int it = 0;
    for (int tile = blockIdx.x; tile < ntiles; tile += gridDim.x, it++) {
        float* cur = (it & 1) ? sX1 : sX0;
        float* nxt = (it & 1) ? sX0 : sX1;
        int ntile = tile + gridDim.x;
        if (ntile < ntiles) prefetch_x(in, in_ld, 0, ntile*TILE_ROWS, 64, nrows, nxt, t, 256);
        CP_COMMIT();
        CP_WAIT1();
        __syncthreads();

        unsigned long long acc[4][4];
#pragma unroll
        for (int r = 0; r < 4; r++)
#pragma unroll
            for (int i = 0; i < 4; i++) acc[r][i] = 0ull;
        gemm_mm(cur, sWt, acc, colg, rowg);

        int rowBase = tile * TILE_ROWS;
#pragma unroll
        for (int r = 0; r < 4; r++) {
            int gr = rowBase + rowg*4 + r;
            if (gr >= nrows) continue;
#pragma unroll
            for (int i = 0; i < 4; i++) {
                float2 p = unpk(acc[r][i]);
                out[(size_t)gr*64 + colg + 16*i] = p.x + p.y + bv[i];
            }
        }
        __syncthreads();
    }
}

// ---- persistent fused GIN MLP ----
__global__ __launch_bounds__(256, 3)
void gin_mlp_p(const float* __restrict__ z,
               const float* __restrict__ W1, const float* __restrict__ b1,
               const float* __restrict__ W2, const float* __restrict__ b2,
               float* __restrict__ out, float* __restrict__ out2,
               int nrows, int ntiles)
{
    extern __shared__ float sm[];
    float* sX0 = sm;
    float* sX1 = sm + CHUNK_F;
    float* sW1 = sm + 2*CHUNK_F;
    float* sW2 = sm + 3*CHUNK_F;
    int t = threadIdx.x;
    int colg = t & 15, rowg = t >> 4;

    gemm_load_w(W1, sW1, t, 256);
    gemm_load_w(W2, sW2, t, 256);

    float bv1[4], bv2[4];
#pragma unroll
    for (int i = 0; i < 4; i++) { bv1[i] = b1[colg + 16*i]; bv2[i] = b2[colg + 16*i]; }

    prefetch_x(z, 64, 0, blockIdx.x*TILE_ROWS, 64, nrows, sX0, t, 256);
    CP_COMMIT();

    int it = 0;
    for (int tile = blockIdx.x; tile < ntiles; tile += gridDim.x, it++) {
        float* cur = (it & 1) ? sX1 : sX0;
        float* nxt = (it & 1) ? sX0 : sX1;
        int ntile = tile + gridDim.x;
        if (ntile < ntiles) prefetch_x(z, 64, 0, ntile*TILE_ROWS, 64, nrows, nxt, t, 256);
        CP_COMMIT();
        CP_WAIT1();
        __syncthreads();

        unsigned long long acc[4][4];
#pragma unroll
        for (int r = 0; r < 4; r++)
#pragma unroll
            for (int i = 0; i < 4; i++) acc[r][i] = 0ull;
        gemm_mm(cur, sW1, acc, colg, rowg);

        __syncwarp();
#pragma unroll
        for (int r = 0; r < 4; r++)
#pragma unroll
            for (int i = 0; i < 4; i++) {
                float2 p = unpk(acc[r][i]);
                cur[(rowg*4 + r)*SX_LD + colg + 16*i] = gelu_f(p.x + p.y + bv1[i]);
                acc[r][i] = 0ull;
            }
        __syncwarp();
        gemm_mm(cur, sW2, acc, colg, rowg);

        int rowBase = tile * TILE_ROWS;
#pragma unroll
        for (int r = 0; r < 4; r++) {
            int gr = rowBase + rowg*4 + r;
            if (gr >= nrows) continue;
#pragma unroll
            for (int i = 0; i < 4; i++) {
                float2 p = unpk(acc[r][i]);
                float val = p.x + p.y + bv2[i];
                int c = colg + 16*i;
                out[(size_t)gr*64 + c]  = val;
                out2[(size_t)gr*384 + c] = val;
            }
        }
        __syncthreads();
    }
}

// ---- persistent fuse GEMM: 512 threads, 128-row tiles, all W resident ----
#define FUSE_ROWS 128
__global__ __launch_bounds__(512, 1)
void gemm_fuse_p(const float* __restrict__ in,
                 const float* __restrict__ W, const float* __restrict__ bias,
                 float* __restrict__ out, int nrows, int ntiles)
{
    extern __shared__ float sm[];
    float* sX0 = sm;
    float* sX1 = sm + FUSE_ROWS*SX_LD;
    float* sW  = sm + 2*FUSE_ROWS*SX_LD;
    int t = threadIdx.x;
    int colg = t & 15, rowg = t >> 4;

#pragma unroll
    for (int c = 0; c < 6; c++) gemm_load_w(W + c*4096, sW + c*CHUNK_F, t, 512);

    float bv[4];
#pragma unroll
    for (int i = 0; i < 4; i++) bv[i] = bias[colg + 16*i];

    prefetch_x(in, 384, 0, blockIdx.x*FUSE_ROWS, 128, nrows, sX0, t, 512);
    CP_COMMIT();

    int it = 0;
    for (int tile = blockIdx.x; tile < ntiles; tile += gridDim.x) {
        unsigned long long acc[4][4];
#pragma unroll
        for (int r = 0; r < 4; r++)
#pragma unroll
            for (int i = 0; i < 4; i++) acc[r][i] = 0ull;

        for (int kc = 0; kc < 6; kc++, it++) {
            float* cur = (it & 1) ? sX1 : sX0;
            float* nxt = (it & 1) ? sX0 : sX1;
            int nt = tile, nk = kc + 1;
            if (nk == 6) { nt = tile + gridDim.x; nk = 0; }
            if (nt < ntiles)
                prefetch_x(in, 384, nk*64, nt*FUSE_ROWS, 128, nrows, nxt, t, 512);
            CP_COMMIT();
            CP_WAIT1();
            __syncthreads();
            gemm_mm(cur, sW + kc*CHUNK_F, acc, colg, rowg);
            __syncthreads();
        }

        int rowBase = tile * FUSE_ROWS;
#pragma unroll
        for (int r = 0; r < 4; r++) {
            int gr = rowBase + rowg*4 + r;
            if (gr >= nrows) continue;
#pragma unroll
            for (int i = 0; i < 4; i++) {
                float2 p = unpk(acc[r][i]);
                out[(size_t)gr*64 + colg + 16*i] = p.x + p.y + bv[i];
            }
        }
    }
}

// ---------------- CSR gathers ----------------
__device__ __forceinline__ float sxor(float v, unsigned s) {
    return __uint_as_float(__float_as_uint(v) ^ s);
}

// persistent: h + inline column stats (sum / sumsq partials per block)
#define AGG_GRID 1480
__global__ __launch_bounds__(256)
void sage_agg_kernel(const float* __restrict__ xt, const float* __restrict__ x,
                     const int* __restrict__ start, const int* __restrict__ cnt,
                     const unsigned* __restrict__ elist, float* __restrict__ h,
                     float* __restrict__ partial, int n)
{
    int lane = threadIdx.x & 31;
    int warp = threadIdx.x >> 5;
    int half = lane >> 4, l16 = lane & 15;
    const float4* xt4 = (const float4*)xt;
    float4 ss  = make_float4(0.f, 0.f, 0.f, 0.f);
    float4 ss2 = make_float4(0.f, 0.f, 0.f, 0.f);

    for (int w = blockIdx.x*8 + warp; w < n; w += AGG_GRID*8) {
        float4 acc  = make_float4(0.f, 0.f, 0.f, 0.f);
        float4 accB = make_float4(0.f, 0.f, 0.f, 0.f);
        int s0 = start[w], c = cnt[w], end = s0 + c;
        int e = s0 + half;
        for (; e + 2 < end; e += 4) {
            unsigned p0 = elist[e], p1 = elist[e+2];
            unsigned sg0 = p0 & 0x80000000u, sg1 = p1 & 0x80000000u;
            float4 v0 = xt4[(size_t)(p0 & 0x7fffffffu)*16 + l16];
            float4 v1 = xt4[(size_t)(p1 & 0x7fffffffu)*16 + l16];
            acc.x  += sxor(v0.x, sg0); acc.y  += sxor(v0.y, sg0);
            acc.z  += sxor(v0.z, sg0); acc.w  += sxor(v0.w, sg0);
            accB.x += sxor(v1.x, sg1); accB.y += sxor(v1.y, sg1);
            accB.z += sxor(v1.z, sg1); accB.w += sxor(v1.w, sg1);
        }
        for (; e < end; e += 2) {
            unsigned p0 = elist[e];
            unsigned sg0 = p0 & 0x80000000u;
            float4 v0 = xt4[(size_t)(p0 & 0x7fffffffu)*16 + l16];
            acc.x += sxor(v0.x, sg0); acc.y += sxor(v0.y, sg0);
            acc.z += sxor(v0.z, sg0); acc.w += sxor(v0.w, sg0);
        }
        acc.x += accB.x; acc.y += accB.y; acc.z += accB.z; acc.w += accB.w;
        acc.x += __shfl_xor_sync(0xffffffffu, acc.x, 16);
        acc.y += __shfl_xor_sync(0xffffffffu, acc.y, 16);
        acc.z += __shfl_xor_sync(0xffffffffu, acc.z, 16);
        acc.w += __shfl_xor_sync(0xffffffffu, acc.w, 16);
        float4 self = xt4[(size_t)w*16 + l16];
        float4 xv   = ((const float4*)x)[(size_t)w*16 + l16];
        float invd = 1.0f / (float)(c + 1);
        float4 o;
        o.x = (acc.x + self.x) * invd + xv.x;
        o.y = (acc.y + self.y) * invd + xv.y;
        o.z = (acc.z + self.z) * invd + xv.z;
        o.w = (acc.w + self.w) * invd + xv.w;
        if (lane < 16) {
            ((float4*)h)[(size_t)w*16 + l16] = o;
            ss.x  += o.x;     ss.y  += o.y;     ss.z  += o.z;     ss.w  += o.w;
            ss2.x += o.x*o.x; ss2.y += o.y*o.y; ss2.z += o.z*o.z; ss2.w += o.w*o.w;
        }
    }

    // block reduction of column stats
    __shared__ float sred[8][128];
    if (lane < 16) {
        *(float4*)&sred[warp][l16*4]      = ss;
        *(float4*)&sred[warp][64 + l16*4] = ss2;
    }
    __syncthreads();
    int t = threadIdx.x;
    if (t < 128) {
        float v = 0.f;
#pragma unroll
        for (int wp = 0; wp < 8; wp++) v += sred[wp][t];
        partial[blockIdx.x*128 + t] = v;
    }
}

// z[n] = x[n] + segsum(x[src]); x rows strided by ld4 float4s
__global__ void gin_agg_kernel(const float* __restrict__ x, int ld4,
                               const int* __restrict__ start, const int* __restrict__ cnt,
                               const unsigned* __restrict__ elist, float* __restrict__ z, int n)
{
    int w = (blockIdx.x * blockDim.x + threadIdx.x) >> 5;
    int lane = threadIdx.x & 31;
    if (w >= n) return;
    int half = lane >> 4, l16 = lane & 15;
    const float4* x4 = (const float4*)x;
    float4 acc  = make_float4(0.f, 0.f, 0.f, 0.f);
    float4 accB = make_float4(0.f, 0.f, 0.f, 0.f);
    int s0 = start[w], c = cnt[w], end = s0 + c;
    int e = s0 + half;
    for (; e + 2 < end; e += 4) {
        unsigned p0 = elist[e], p1 = elist[e+2];
        float4 v0 = x4[(size_t)(p0 & 0x7fffffffu)*ld4 + l16];
        float4 v1 = x4[(size_t)(p1 & 0x7fffffffu)*ld4 + l16];
        acc.x  += v0.x; acc.y  += v0.y; acc.z  += v0.z; acc.w  += v0.w;
        accB.x += v1.x; accB.y += v1.y; accB.z += v1.z; accB.w += v1.w;
    }
    for (; e < end; e += 2) {
        unsigned p0 = elist[e];
        float4 v0 = x4[(size_t)(p0 & 0x7fffffffu)*ld4 + l16];
        acc.x += v0.x; acc.y += v0.y; acc.z += v0.z; acc.w += v0.w;
    }
    acc.x += accB.x; acc.y += accB.y; acc.z += accB.z; acc.w += accB.w;
    acc.x += __shfl_xor_sync(0xffffffffu, acc.x, 16);
    acc.y += __shfl_xor_sync(0xffffffffu, acc.y, 16);
    acc.z += __shfl_xor_sync(0xffffffffu, acc.z, 16);
    acc.w += __shfl_xor_sync(0xffffffffu, acc.w, 16);
    float4 self = x4[(size_t)w*ld4 + l16];
    float4 o;
    o.x = acc.x + self.x; o.y = acc.y + self.y;
    o.z = acc.z + self.z; o.w = acc.w + self.w;
    if (lane < 16) ((float4*)z)[(size_t)w*16 + l16] = o;
}

// ---------------- graph-norm finalize (sums 1480 block partials) ----------------
__global__ void gnfin_kernel(const float* __restrict__ partial,
                             const float* __restrict__ nw, const float* __restrict__ nb,
                             const float* __restrict__ rsw, const float* __restrict__ rsb,
                             const float* __restrict__ rbw, const float* __restrict__ rbb,
                             const float* __restrict__ rate_b, float* __restrict__ gn, int n)
{
    int f = threadIdx.x;  // 64 threads
    double s = 0.0, s2 = 0.0;
#pragma unroll 4
    for (int b = 0; b < AGG_GRID; b++) {
        s  += (double)partial[b*128 + f];
        s2 += (double)partial[b*128 + 64 + f];
    }
    float rate = rate_b[0];
    double m   = s / (double)n;
    double var = s2 / (double)n - m*m;
    gn[f]       = (float)m;
    gn[64 + f]  = rsqrtf((float)var + 1e-5f);
    gn[128 + f] = nw[f] + (rsw[f]*rate + rsb[f]);
    gn[192 + f] = nb[f] + (rbw[f]*rate + rbb[f]);
}

// gelu(norm(h)) -> xd slice (consumers read strided)
__global__ void gnapply_kernel(const float* __restrict__ h, const float* __restrict__ gn,
                               float* __restrict__ xd, int n)
{
    int idx = blockIdx.x * blockDim.x + threadIdx.x;
    if (idx >= n*32) return;
    int j = idx & 31, r = idx >> 5;
    int f = j*2;
    float2 v = ((const float2*)h)[idx];
    float t0 = (v.x - gn[f])   * gn[64+f]   * gn[128+f]   + gn[192+f];
    float t1 = (v.y - gn[f+1]) * gn[64+f+1] * gn[128+f+1] + gn[192+f+1];
    float2 o = make_float2(gelu_f(t0), gelu_f(t1));
    *(float2*)(xd + (size_t)r*384 + f) = o;
}

// ---------------- fused readout: 8 rows/warp, smem-broadcast activations ----------
#define RO_THREADS 512
#define RO_WARPS   (RO_THREADS/32)
#define RO_ROWS    (RO_WARPS*8)
#define SA_LD 132
#define RO_SMEM ((8192 + 16384 + 7*128 + RO_WARPS*8*SA_LD) * 4)

__global__ __launch_bounds__(RO_THREADS)
void readout_kernel(const float* __restrict__ xf,
                    const float* __restrict__ W1, const float* __restrict__ b1,
                    const float* __restrict__ g1, const float* __restrict__ be1,
                    const float* __restrict__ W2, const float* __restrict__ b2,
                    const float* __restrict__ g2, const float* __restrict__ be2,
                    const float* __restrict__ W3, const float* __restrict__ b3,
                    float* __restrict__ prob, int nrows)
{
    extern __shared__ float sm[];
    float* sW1 = sm;
    float* sW2 = sm + 8192;
    float* sP  = sm + 8192 + 16384;
    float* sA  = sP + 7*128;
    int t = threadIdx.x;
    for (int v = t; v < 8192;  v += RO_THREADS) sW1[v] = W1[v];
    for (int v = t; v < 16384; v += RO_THREADS) sW2[v] = W2[v];
    if (t < 128) {
        sP[t]       = b1[t];  sP[128 + t] = g1[t];  sP[256 + t] = be1[t];
        sP[384 + t] = b2[t];  sP[512 + t] = g2[t];  sP[640 + t] = be2[t];
        sP[768 + t] = W3[t];
    }

    int lane = t & 31, wp = t >> 5;
    int row0 = blockIdx.x * RO_ROWS + wp * 8;
    float* myA = sA + wp * 8 * SA_LD;

#pragma unroll
    for (int r = 0; r < 8; r++) {
        int gr = min(row0 + r, nrows - 1);
        myA[r*SA_LD + lane]      = xf[(size_t)gr*64 + lane];
        myA[r*SA_LD + 32 + lane] = xf[(size_t)gr*64 + 32 + lane];
    }
    __syncthreads();

    float bias3 = b3[0];

    unsigned long long a0[8], a1[8];
    {
        F4U bi; bi.f = *(const float4*)(sP + lane*4);
#pragma unroll
        for (int r = 0; r < 8; r++) { a0[r] = bi.u[0]; a1[r] = bi.u[1]; }
    }
#pragma unroll 4
    for (int k = 0; k < 64; k++) {
        F4U wv; wv.f = *(const float4*)(sW1 + k*128 + lane*4);
#pragma unroll
        for (int r = 0; r < 8; r++) {
            unsigned long long xp = dup2(myA[r*SA_LD + k]);
            ffma2(a0[r], xp, wv.u[0]);
            ffma2(a1[r], xp, wv.u[1]);
        }
    }

    float A[8][4];
#pragma unroll
    for (int r = 0; r < 8; r++) {
        float2 p0 = unpk(a0[r]), p1 = unpk(a1[r]);
        A[r][0] = p0.x; A[r][1] = p0.y; A[r][2] = p1.x; A[r][3] = p1.y;
    }
    {
        float4 gg = *(const float4*)(sP + 128 + lane*4);
        float4 bb = *(const float4*)(sP + 256 + lane*4);
        __syncwarp();
#pragma unroll
        for (int r = 0; r < 8; r++) {
            float s  = A[r][0] + A[r][1] + A[r][2] + A[r][3];
            float s2 = A[r][0]*A[r][0] + A[r][1]*A[r][1] + A[r][2]*A[r][2] + A[r][3]*A[r][3];
            for (int o = 16; o; o >>= 1) {
                s  += __shfl_xor_sync(0xffffffffu, s,  o);
                s2 += __shfl_xor_sync(0xffffffffu, s2, o);
            }
            float m   = s  * (1.0f/128.0f);
            float var = s2 * (1.0f/128.0f) - m*m;
            float rs  = rsqrtf(var + 1e-5f);
            float4 hv;
            hv.x = fmaxf((A[r][0] - m)*rs*gg.x + bb.x, 0.f);
            hv.y = fmaxf((A[r][1] - m)*rs*gg.y + bb.y, 0.f);
            hv.z = fmaxf((A[r][2] - m)*rs*gg.z + bb.z, 0.f);
            hv.w = fmaxf((A[r][3] - m)*rs*gg.w + bb.w, 0.f);
            *(float4*)(myA + r*SA_LD + lane*4) = hv;
        }
        __syncwarp();
    }

    unsigned long long c0[8], c1[8];
    {
        F4U bi; bi.f = *(const float4*)(sP + 384 + lane*4);
#pragma unroll
        for (int r = 0; r < 8; r++) { c0[r] = bi.u[0]; c1[r] = bi.u[1]; }
    }
#pragma unroll 4
    for (int k = 0; k < 128; k++) {
        F4U wv; wv.f = *(const float4*)(sW2 + k*128 + lane*4);
#pragma unroll
        for (int r = 0; r < 8; r++) {
            unsigned long long hp = dup2(myA[r*SA_LD + k]);
            ffma2(c0[r], hp, wv.u[0]);
            ffma2(c1[r], hp, wv.u[1]);
        }
    }

#pragma unroll
    for (int r = 0; r < 8; r++) {
        float2 p0 = unpk(c0[r]), p1 = unpk(c1[r]);
        A[r][0] = p0.x; A[r][1] = p0.y; A[r][2] = p1.x; A[r][3] = p1.y;
    }
    {
        float4 gg = *(const float4*)(sP + 512 + lane*4);
        float4 bb = *(const float4*)(sP + 640 + lane*4);
        float4 w3v = *(const float4*)(sP + 768 + lane*4);
#pragma unroll
        for (int r = 0; r < 8; r++) {
            float s  = A[r][0] + A[r][1] + A[r][2] + A[r][3];
            float s2 = A[r][0]*A[r][0] + A[r][1]*A[r][1] + A[r][2]*A[r][2] + A[r][3]*A[r][3];
            for (int o = 16; o; o >>= 1) {
                s  += __shfl_xor_sync(0xffffffffu, s,  o);
                s2 += __shfl_xor_sync(0xffffffffu, s2, o);
            }
            float m   = s  * (1.0f/128.0f);
            float var = s2 * (1.0f/128.0f) - m*m;
            float rs  = rsqrtf(var + 1e-5f);
            float v0 = fmaxf((A[r][0] - m)*rs*gg.x + bb.x, 0.f);
            float v1 = fmaxf((A[r][1] - m)*rs*gg.y + bb.y, 0.f);
            float v2 = fmaxf((A[r][2] - m)*rs*gg.z + bb.z, 0.f);
            float v3 = fmaxf((A[r][3] - m)*rs*gg.w + bb.w, 0.f);
            float p = v0*w3v.x + v1*w3v.y + v2*w3v.z + v3*w3v.w;
            for (int o = 16; o; o >>= 1) p += __shfl_xor_sync(0xffffffffu, p, o);
            if (lane == 0 && row0 + r < nrows) prob[row0 + r] = 1.0f / (1.0f + expf(-(p + bias3)));
        }
    }
}

// ---------------- host driver ----------------
extern "C" void kernel_launch(void* const* d_in, const int* in_sizes, int n_in,
                              void* d_out, int out_size)
{
    const float* init_emb    = (const float*)d_in[0];
    const int*   ei          = (const int*)  d_in[1];
    const float* rate_b      = (const float*)d_in[2];
    const float* sage_lin_W  = (const float*)d_in[3];
    const float* sage_lin_b  = (const float*)d_in[4];
    const float* sage_norm_w = (const float*)d_in[5];
    const float* sage_norm_b = (const float*)d_in[6];
    const float* sage_rs_w   = (const float*)d_in[7];
    const float* sage_rs_b   = (const float*)d_in[8];
    const float* sage_rb_w   = (const float*)d_in[9];
    const float* sage_rb_b   = (const float*)d_in[10];
    const float* gin_W1      = (const float*)d_in[11];
    const float* gin_b1      = (const float*)d_in[12];
    const float* gin_W2      = (const float*)d_in[13];
    const float* gin_b2      = (const float*)d_in[14];
    const float* fuse_W      = (const float*)d_in[15];
    const float* fuse_b      = (const float*)d_in[16];
    const float* ro_W1       = (const float*)d_in[17];
    const float* ro_b1       = (const float*)d_in[18];
    const float* ro_ln1_g    = (const float*)d_in[19];
    const float* ro_ln1_b    = (const float*)d_in[20];
    const float* ro_W2       = (const float*)d_in[21];
    const float* ro_b2       = (const float*)d_in[22];
    const float* ro_ln2_g    = (const float*)d_in[23];
    const float* ro_ln2_b    = (const float*)d_in[24];
    const float* ro_W3       = (const float*)d_in[25];
    const float* ro_b3       = (const float*)d_in[26];
    float* out = (float*)d_out;

    float *px, *pxt, *ph, *pxd, *pgn, *ppart;
    int *pcnt, *pfill, *pstart, *pbsum;
    unsigned* pelist;
    cudaGetSymbolAddress((void**)&px,    g_x);
    cudaGetSymbolAddress((void**)&pxt,   g_xt);
    cudaGetSymbolAddress((void**)&ph,    g_h);
    cudaGetSymbolAddress((void**)&pxd,   g_xd);
    cudaGetSymbolAddress((void**)&pgn,   g_gn);
    cudaGetSymbolAddress((void**)&ppart, g_part);
    cudaGetSymbolAddress((void**)&pcnt,  g_cnt);
    cudaGetSymbolAddress((void**)&pfill, g_fill);
    cudaGetSymbolAddress((void**)&pstart,g_start);
    cudaGetSymbolAddress((void**)&pbsum, g_bsum);
    cudaGetSymbolAddress((void**)&pelist,g_elist);

    const int nblk    = (NN + SCAN_BS - 1) / SCAN_BS;
    const int egrid   = (EE + 255) / 256;
    const int ntiles  = (NN + TILE_ROWS - 1) / TILE_ROWS;    // 1563
    const int ftiles  = (NN + FUSE_ROWS - 1) / FUSE_ROWS;    // 782
    const int agrid   = (NN + 7) / 8;                        // 12500
    const int rgrid   = (NN + RO_ROWS - 1) / RO_ROWS;        // 782

    const int smem64   = 3 * CHUNK_F * 4;                    // 52KB
    const int smemMlp  = 4 * CHUNK_F * 4;                    // 70KB
    const int smemFuse = (2*FUSE_ROWS*SX_LD + 6*CHUNK_F)*4;  // 174KB

    cudaFuncSetAttribute(gemm64_p,    cudaFuncAttributeMaxDynamicSharedMemorySize, smem64);
    cudaFuncSetAttribute(gin_mlp_p,   cudaFuncAttributeMaxDynamicSharedMemorySize, smemMlp);
    cudaFuncSetAttribute(gemm_fuse_p, cudaFuncAttributeMaxDynamicSharedMemorySize, smemFuse);
    cudaFuncSetAttribute(readout_kernel, cudaFuncAttributeMaxDynamicSharedMemorySize, RO_SMEM);

    // ---- CSR build (sage GEMM 0 interleaved at profiling slot 3) ----
    zero_all_kernel<<<(NN + 255)/256, 256>>>(pcnt, pfill);
    count_kernel<<<egrid, 256>>>(ei, pcnt);
    scan_block_kernel<<<nblk, SCAN_BS>>>(pcnt, pstart, pbsum, NN);
    gemm64_p<<<P_GRID, 256, smem64>>>(init_emb, 64, sage_lin_W, sage_lin_b,
                                      pxt, NN, ntiles);
    scan_part_kernel<<<1, SCAN_BS>>>(pbsum, nblk);
    scan_add_kernel<<<nblk, SCAN_BS>>>(pstart, pbsum, NN);
    fill_kernel<<<egrid, 256>>>(ei, pstart, pfill, pelist);

    // ---- 3 SAGE+GIN pairs ----
    for (int i = 0; i < 3; i++) {
        const float* xin = (i == 0) ? init_emb : px;
        if (i > 0)
            gemm64_p<<<P_GRID, 256, smem64>>>(xin, 64, sage_lin_W + i*4096,
                                              sage_lin_b + i*64, pxt, NN, ntiles);
        sage_agg_kernel<<<AGG_GRID, 256>>>(pxt, xin, pstart, pcnt, pelist, ph, ppart, NN);
        gnfin_kernel<<<1, 64>>>(ppart,
                                sage_norm_w + i*64, sage_norm_b + i*64,
                                sage_rs_w + i*64, sage_rs_b + i*64,
                                sage_rb_w + i*64, sage_rb_b + i*64,
                                rate_b, pgn, NN);
        gnapply_kernel<<<(NN*32 + 255)/256, 256>>>(ph, pgn, pxd + (size_t)(2*i)*64, NN);
        gin_agg_kernel<<<agrid, 256>>>(pxd + (size_t)(2*i)*64, 96,
                                       pstart, pcnt, pelist, pxt, NN);
        gin_mlp_p<<<P_GRID, 256, smemMlp>>>(pxt, gin_W1 + i*4096, gin_b1 + i*64,
                                            gin_W2 + i*4096, gin_b2 + i*64,
                                            px, pxd + (size_t)(2*i+1)*64, NN, ntiles);
    }

    // ---- fuse: x_final = x_dense @ fuse_W + fuse_b ----
    gemm_fuse_p<<<148, 512, smemFuse>>>(pxd, fuse_W, fuse_b, out, NN, ftiles);

    // ---- fused readout -> prob ----
    readout_kernel<<<rgrid, RO_THREADS, RO_SMEM>>>(
        out, ro_W1, ro_b1, ro_ln1_g, ro_ln1_b,
        ro_W2, ro_b2, ro_ln2_g, ro_ln2_b,
        ro_W3, ro_b3, out + (size_t)(out_size - NN), NN);
}

// round 9
// speedup vs baseline: 1.7838x; 1.7838x over previous
#include <cuda_runtime.h>
#include <math.h>

#define NN 100000
#define EE 1250000
#define DD 64

// ---------------- scratch (device globals) ----------------
__device__ float    g_x   [NN*DD];
__device__ float    g_xt  [NN*DD];
__device__ float    g_h   [NN*DD];
__device__ float    g_xd  [NN*6*DD];      // x_dense [N,384]
__device__ int      g_cnt [NN];
__device__ int      g_fill[NN];
__device__ int      g_start[NN];
__device__ unsigned g_elist[EE];          // src | signbit<<31
__device__ int      g_bsum[1024];
__device__ double   g_csum[3*128];
__device__ float    g_gn  [256];

__device__ __forceinline__ float gelu_f(float v) {
    return 0.5f * v * (1.0f + erff(v * 0.70710678118654752440f));
}

// packed fp32x2 helpers (sm_100+)
__device__ __forceinline__ void ffma2(unsigned long long& d, unsigned long long a,
                                      unsigned long long b) {
    asm("fma.rn.f32x2 %0, %1, %2, %0;" : "+l"(d) : "l"(a), "l"(b));
}
__device__ __forceinline__ float2 unpk(unsigned long long v) {
    float2 f;
    asm("mov.b64 {%0, %1}, %2;" : "=f"(f.x), "=f"(f.y) : "l"(v));
    return f;
}
union F4U { float4 f; unsigned long long u[2]; };

// cp.async helpers
__device__ __forceinline__ unsigned smem_u32(const void* p) {
    return (unsigned)__cvta_generic_to_shared(p);
}
__device__ __forceinline__ void cpasync16(unsigned dst, const void* src) {
    asm volatile("cp.async.cg.shared.global [%0], [%1], 16;" :: "r"(dst), "l"(src));
}
#define CP_COMMIT() asm volatile("cp.async.commit_group;" ::: "memory")
#define CP_WAIT1()  asm volatile("cp.async.wait_group 1;" ::: "memory")

// ---------------- utility ----------------
__global__ void zero_all_kernel(int* cnt, int* fill, double* csum) {
    int i = blockIdx.x * blockDim.x + threadIdx.x;
    if (i < NN) { cnt[i] = 0; fill[i] = 0; }
    if (i < 3*128) csum[i] = 0.0;
}

// ---------------- CSR build ----------------
__global__ void count_kernel(const int* __restrict__ ei, int* __restrict__ cnt) {
    int e = blockIdx.x * blockDim.x + threadIdx.x;
    if (e < EE) atomicAdd(&cnt[ei[e*3 + 1]], 1);
}

#define SCAN_BS 1024
__global__ void scan_block_kernel(const int* __restrict__ cnt, int* __restrict__ excl,
                                  int* __restrict__ bsum, int n) {
    __shared__ int s[SCAN_BS];
    int i = blockIdx.x * SCAN_BS + threadIdx.x;
    int v = (i < n) ? cnt[i] : 0;
    s[threadIdx.x] = v;
    __syncthreads();
    for (int off = 1; off < SCAN_BS; off <<= 1) {
        int t = (threadIdx.x >= off) ? s[threadIdx.x - off] : 0;
        __syncthreads();
        s[threadIdx.x] += t;
        __syncthreads();
    }
    if (i < n) excl[i] = s[threadIdx.x] - v;
    if (threadIdx.x == SCAN_BS - 1) bsum[blockIdx.x] = s[SCAN_BS - 1];
}
__global__ void scan_part_kernel(int* __restrict__ bs, int nb) {
    __shared__ int s[SCAN_BS];
    int v = (threadIdx.x < nb) ? bs[threadIdx.x] : 0;
    s[threadIdx.x] = v;
    __syncthreads();
    for (int off = 1; off < SCAN_BS; off <<= 1) {
        int t = (threadIdx.x >= off) ? s[threadIdx.x - off] : 0;
        __syncthreads();
        s[threadIdx.x] += t;
        __syncthreads();
    }
    if (threadIdx.x < nb) bs[threadIdx.x] = s[threadIdx.x] - v;
}
__global__ void scan_add_kernel(int* __restrict__ excl, const int* __restrict__ bs, int n) {
    int i = blockIdx.x * SCAN_BS + threadIdx.x;
    if (i < n) excl[i] += bs[blockIdx.x];
}
__global__ void fill_kernel(const int* __restrict__ ei, const int* __restrict__ start,
                            int* __restrict__ fill, unsigned* __restrict__ elist) {
    int e = blockIdx.x * blockDim.x + threadIdx.x;
    if (e >= EE) return;
    int src = ei[e*3 + 0];
    int dst = ei[e*3 + 1];
    int sg  = ei[e*3 + 2];
    int pos = start[dst] + atomicAdd(&fill[dst], 1);
    elist[pos] = (unsigned)src | (sg < 0 ? 0x80000000u : 0u);
}

// ---------------- persistent GEMM infrastructure -------------------
#define TILE_ROWS 64
#define SX_LD 68
#define CHUNK_F (64*SX_LD)
#define P_GRID 444

__device__ __forceinline__ void gemm_load_w(const float* __restrict__ W, float* sWt, int t) {
    const float4* W4 = (const float4*)W;
#pragma unroll
    for (int v = t; v < 1024; v += 256) {
        int k = v >> 4, j4 = v & 15;
        float4 w = W4[k*16 + j4];
        sWt[(j4*4+0)*SX_LD + k] = w.x;
        sWt[(j4*4+1)*SX_LD + k] = w.y;
        sWt[(j4*4+2)*SX_LD + k] = w.z;
        sWt[(j4*4+3)*SX_LD + k] = w.w;
    }
}

__device__ __forceinline__ void prefetch_x(const float* __restrict__ in, int in_ld, int kc,
                                           int rowBase, int nrows, float* buf, int t) {
#pragma unroll
    for (int v = t; v < 1024; v += 256) {
        int r = v >> 4, c4 = v & 15;
        int gr = rowBase + r;
        if (gr >= nrows) gr = nrows - 1;
        cpasync16(smem_u32(buf + r*SX_LD + c4*4), in + (size_t)gr*in_ld + kc + c4*4);
    }
}

__device__ __forceinline__ void gemm_mm(const float* sX, const float* sWt,
                                        unsigned long long acc[4][4], int colg, int rowg) {
#pragma unroll
    for (int k4 = 0; k4 < 16; k4++) {
        F4U wv[4];
#pragma unroll
        for (int i = 0; i < 4; i++)
            wv[i].f = *(const float4*)(sWt + (colg + 16*i)*SX_LD + k4*4);
#pragma unroll
        for (int r = 0; r < 4; r++) {
            F4U xv;
            xv.f = *(const float4*)(sX + (rowg*4 + r)*SX_LD + k4*4);
#pragma unroll
            for (int i = 0; i < 4; i++) {
                ffma2(acc[r][i], xv.u[0], wv[i].u[0]);
                ffma2(acc[r][i], xv.u[1], wv[i].u[1]);
            }
        }
    }
}

// ---- persistent K=64 GEMM: out = in @ W + b ----
__global__ __launch_bounds__(256, 3)
void gemm64_p(const float* __restrict__ in, int in_ld,
              const float* __restrict__ W, const float* __restrict__ bias,
              float* __restrict__ out, int nrows, int ntiles)
{
    extern __shared__ float sm[];
    float* sX0 = sm;
    float* sX1 = sm + CHUNK_F;
    float* sWt = sm + 2*CHUNK_F;
    int t = threadIdx.x;
    int colg = t & 15, rowg = t >> 4;

    gemm_load_w(W, sWt, t);

    float bv[4];
#pragma unroll
    for (int i = 0; i < 4; i++) bv[i] = bias[colg + 16*i];

    prefetch_x(in, in_ld, 0, blockIdx.x*TILE_ROWS, nrows, sX0, t);
    CP_COMMIT();

    int it = 0;
    for (int tile = blockIdx.x; tile < ntiles; tile += gridDim.x, it++) {
        float* cur = (it & 1) ? sX1 : sX0;
        float* nxt = (it & 1) ? sX0 : sX1;
        int ntile = tile + gridDim.x;
        if (ntile < ntiles) prefetch_x(in, in_ld, 0, ntile*TILE_ROWS, nrows, nxt, t);
        CP_COMMIT();
        CP_WAIT1();
        __syncthreads();

        unsigned long long acc[4][4];
#pragma unroll
        for (int r = 0; r < 4; r++)
#pragma unroll
            for (int i = 0; i < 4; i++) acc[r][i] = 0ull;
        gemm_mm(cur, sWt, acc, colg, rowg);

        int rowBase = tile * TILE_ROWS;
#pragma unroll
        for (int r = 0; r < 4; r++) {
            int gr = rowBase + rowg*4 + r;
            if (gr >= nrows) continue;
#pragma unroll
            for (int i = 0; i < 4; i++) {
                float2 p = unpk(acc[r][i]);
                out[(size_t)gr*64 + colg + 16*i] = p.x + p.y + bv[i];
            }
        }
        __syncthreads();
    }
}

// ---- persistent fused GIN MLP ----
__global__ __launch_bounds__(256, 3)
void gin_mlp_p(const float* __restrict__ z,
               const float* __restrict__ W1, const float* __restrict__ b1,
               const float* __restrict__ W2, const float* __restrict__ b2,
               float* __restrict__ out, float* __restrict__ out2,
               int nrows, int ntiles)
{
    extern __shared__ float sm[];
    float* sX0 = sm;
    float* sX1 = sm + CHUNK_F;
    float* sW1 = sm + 2*CHUNK_F;
    float* sW2 = sm + 3*CHUNK_F;
    int t = threadIdx.x;
    int colg = t & 15, rowg = t >> 4;

    gemm_load_w(W1, sW1, t);
    gemm_load_w(W2, sW2, t);

    float bv1[4], bv2[4];
#pragma unroll
    for (int i = 0; i < 4; i++) { bv1[i] = b1[colg + 16*i]; bv2[i] = b2[colg + 16*i]; }

    prefetch_x(z, 64, 0, blockIdx.x*TILE_ROWS, nrows, sX0, t);
    CP_COMMIT();

    int it = 0;
    for (int tile = blockIdx.x; tile < ntiles; tile += gridDim.x, it++) {
        float* cur = (it & 1) ? sX1 : sX0;
        float* nxt = (it & 1) ? sX0 : sX1;
        int ntile = tile + gridDim.x;
        if (ntile < ntiles) prefetch_x(z, 64, 0, ntile*TILE_ROWS, nrows, nxt, t);
        CP_COMMIT();
        CP_WAIT1();
        __syncthreads();

        unsigned long long acc[4][4];
#pragma unroll
        for (int r = 0; r < 4; r++)
#pragma unroll
            for (int i = 0; i < 4; i++) acc[r][i] = 0ull;
        gemm_mm(cur, sW1, acc, colg, rowg);

        __syncwarp();
#pragma unroll
        for (int r = 0; r < 4; r++)
#pragma unroll
            for (int i = 0; i < 4; i++) {
                float2 p = unpk(acc[r][i]);
                cur[(rowg*4 + r)*SX_LD + colg + 16*i] = gelu_f(p.x + p.y + bv1[i]);
                acc[r][i] = 0ull;
            }
        __syncwarp();
        gemm_mm(cur, sW2, acc, colg, rowg);

        int rowBase = tile * TILE_ROWS;
#pragma unroll
        for (int r = 0; r < 4; r++) {
            int gr = rowBase + rowg*4 + r;
            if (gr >= nrows) continue;
#pragma unroll
            for (int i = 0; i < 4; i++) {
                float2 p = unpk(acc[r][i]);
                float val = p.x + p.y + bv2[i];
                int c = colg + 16*i;
                out[(size_t)gr*64 + c]  = val;
                out2[(size_t)gr*384 + c] = val;
            }
        }
        __syncthreads();
    }
}

// ---- persistent fuse GEMM: K=384, all W chunks resident (R6 version) ----
__global__ __launch_bounds__(256, 1)
void gemm_fuse_p(const float* __restrict__ in,
                 const float* __restrict__ W, const float* __restrict__ bias,
                 float* __restrict__ out, int nrows, int ntiles)
{
    extern __shared__ float sm[];
    float* sX0 = sm;
    float* sX1 = sm + CHUNK_F;
    float* sW  = sm + 2*CHUNK_F;   // 6 chunks
    int t = threadIdx.x;
    int colg = t & 15, rowg = t >> 4;

#pragma unroll
    for (int c = 0; c < 6; c++) gemm_load_w(W + c*4096, sW + c*CHUNK_F, t);

    float bv[4];
#pragma unroll
    for (int i = 0; i < 4; i++) bv[i] = bias[colg + 16*i];

    prefetch_x(in, 384, 0, blockIdx.x*TILE_ROWS, nrows, sX0, t);
    CP_COMMIT();

    int it = 0;
    for (int tile = blockIdx.x; tile < ntiles; tile += gridDim.x) {
        unsigned long long acc[4][4];
#pragma unroll
        for (int r = 0; r < 4; r++)
#pragma unroll
            for (int i = 0; i < 4; i++) acc[r][i] = 0ull;

        for (int kc = 0; kc < 6; kc++, it++) {
            float* cur = (it & 1) ? sX1 : sX0;
            float* nxt = (it & 1) ? sX0 : sX1;
            int nt = tile, nk = kc + 1;
            if (nk == 6) { nt = tile + gridDim.x; nk = 0; }
            if (nt < ntiles)
                prefetch_x(in, 384, nk*64, nt*TILE_ROWS, nrows, nxt, t);
            CP_COMMIT();
            CP_WAIT1();
            __syncthreads();
            gemm_mm(cur, sW + kc*CHUNK_F, acc, colg, rowg);
            __syncthreads();
        }

        int rowBase = tile * TILE_ROWS;
#pragma unroll
        for (int r = 0; r < 4; r++) {
            int gr = rowBase + rowg*4 + r;
            if (gr >= nrows) continue;
#pragma unroll
            for (int i = 0; i < 4; i++) {
                float2 p = unpk(acc[r][i]);
                out[(size_t)gr*64 + colg + 16*i] = p.x + p.y + bv[i];
            }
        }
    }
}

// ---------------- CSR gathers: half-warp float4, 4 edges in flight ----------------
__device__ __forceinline__ float sxor(float v, unsigned s) {
    return __uint_as_float(__float_as_uint(v) ^ s);
}

__global__ void sage_agg_kernel(const float* __restrict__ xt, const float* __restrict__ x,
                                const int* __restrict__ start, const int* __restrict__ cnt,
                                const unsigned* __restrict__ elist, float* __restrict__ h, int n)
{
    int w = (blockIdx.x * blockDim.x + threadIdx.x) >> 5;
    int lane = threadIdx.x & 31;
    if (w >= n) return;
    int half = lane >> 4, l16 = lane & 15;
    const float4* xt4 = (const float4*)xt;
    float4 acc  = make_float4(0.f, 0.f, 0.f, 0.f);
    float4 accB = make_float4(0.f, 0.f, 0.f, 0.f);
    int s0 = start[w], c = cnt[w], end = s0 + c;
    int e = s0 + half;
    for (; e + 2 < end; e += 4) {
        unsigned p0 = elist[e], p1 = elist[e+2];
        unsigned sg0 = p0 & 0x80000000u, sg1 = p1 & 0x80000000u;
        float4 v0 = xt4[(size_t)(p0 & 0x7fffffffu)*16 + l16];
        float4 v1 = xt4[(size_t)(p1 & 0x7fffffffu)*16 + l16];
        acc.x  += sxor(v0.x, sg0); acc.y  += sxor(v0.y, sg0);
        acc.z  += sxor(v0.z, sg0); acc.w  += sxor(v0.w, sg0);
        accB.x += sxor(v1.x, sg1); accB.y += sxor(v1.y, sg1);
        accB.z += sxor(v1.z, sg1); accB.w += sxor(v1.w, sg1);
    }
    for (; e < end; e += 2) {
        unsigned p0 = elist[e];
        unsigned sg0 = p0 & 0x80000000u;
        float4 v0 = xt4[(size_t)(p0 & 0x7fffffffu)*16 + l16];
        acc.x += sxor(v0.x, sg0); acc.y += sxor(v0.y, sg0);
        acc.z += sxor(v0.z, sg0); acc.w += sxor(v0.w, sg0);
    }
    acc.x += accB.x; acc.y += accB.y; acc.z += accB.z; acc.w += accB.w;
    acc.x += __shfl_xor_sync(0xffffffffu, acc.x, 16);
    acc.y += __shfl_xor_sync(0xffffffffu, acc.y, 16);
    acc.z += __shfl_xor_sync(0xffffffffu, acc.z, 16);
    acc.w += __shfl_xor_sync(0xffffffffu, acc.w, 16);
    float4 self = xt4[(size_t)w*16 + l16];
    float4 xv   = ((const float4*)x)[(size_t)w*16 + l16];
    float invd = 1.0f / (float)(c + 1);
    float4 o;
    o.x = (acc.x + self.x) * invd + xv.x;
    o.y = (acc.y + self.y) * invd + xv.y;
    o.z = (acc.z + self.z) * invd + xv.z;
    o.w = (acc.w + self.w) * invd + xv.w;
    if (lane < 16) ((float4*)h)[(size_t)w*16 + l16] = o;
}

// z[n] = x[n] + segsum(x[src]); x rows strided by ld4 float4s
__global__ void gin_agg_kernel(const float* __restrict__ x, int ld4,
                               const int* __restrict__ start, const int* __restrict__ cnt,
                               const unsigned* __restrict__ elist, float* __restrict__ z, int n)
{
    int w = (blockIdx.x * blockDim.x + threadIdx.x) >> 5;
    int lane = threadIdx.x & 31;
    if (w >= n) return;
    int half = lane >> 4, l16 = lane & 15;
    const float4* x4 = (const float4*)x;
    float4 acc  = make_float4(0.f, 0.f, 0.f, 0.f);
    float4 accB = make_float4(0.f, 0.f, 0.f, 0.f);
    int s0 = start[w], c = cnt[w], end = s0 + c;
    int e = s0 + half;
    for (; e + 2 < end; e += 4) {
        unsigned p0 = elist[e], p1 = elist[e+2];
        float4 v0 = x4[(size_t)(p0 & 0x7fffffffu)*ld4 + l16];
        float4 v1 = x4[(size_t)(p1 & 0x7fffffffu)*ld4 + l16];
        acc.x  += v0.x; acc.y  += v0.y; acc.z  += v0.z; acc.w  += v0.w;
        accB.x += v1.x; accB.y += v1.y; accB.z += v1.z; accB.w += v1.w;
    }
    for (; e < end; e += 2) {
        unsigned p0 = elist[e];
        float4 v0 = x4[(size_t)(p0 & 0x7fffffffu)*ld4 + l16];
        acc.x += v0.x; acc.y += v0.y; acc.z += v0.z; acc.w += v0.w;
    }
    acc.x += accB.x; acc.y += accB.y; acc.z += accB.z; acc.w += accB.w;
    acc.x += __shfl_xor_sync(0xffffffffu, acc.x, 16);
    acc.y += __shfl_xor_sync(0xffffffffu, acc.y, 16);
    acc.z += __shfl_xor_sync(0xffffffffu, acc.z, 16);
    acc.w += __shfl_xor_sync(0xffffffffu, acc.w, 16);
    float4 self = x4[(size_t)w*ld4 + l16];
    float4 o;
    o.x = acc.x + self.x; o.y = acc.y + self.y;
    o.z = acc.z + self.z; o.w = acc.w + self.w;
    if (lane < 16) ((float4*)z)[(size_t)w*16 + l16] = o;
}

// ---------------- graph-norm column stats ----------------
__global__ void colsum_kernel(const float* __restrict__ h, double* __restrict__ csum,
                              double* __restrict__ csumsq, int n)
{
    int f = threadIdx.x & 63, q = threadIdx.x >> 6;
    float s = 0.f, s2 = 0.f;
    for (int r = blockIdx.x*4 + q; r < n; r += gridDim.x*4) {
        float v = h[(size_t)r*64 + f];
        s += v; s2 += v*v;
    }
    __shared__ float ss[256], ssq[256];
    ss[threadIdx.x] = s; ssq[threadIdx.x] = s2;
    __syncthreads();
    if (q == 0) {
        s  = ss[f]  + ss[64+f]  + ss[128+f]  + ss[192+f];
        s2 = ssq[f] + ssq[64+f] + ssq[128+f] + ssq[192+f];
        atomicAdd(&csum[f],   (double)s);
        atomicAdd(&csumsq[f], (double)s2);
    }
}

__global__ void gnfin_kernel(const double* __restrict__ csum, const double* __restrict__ csumsq,
                             const float* __restrict__ nw, const float* __restrict__ nb,
                             const float* __restrict__ rsw, const float* __restrict__ rsb,
                             const float* __restrict__ rbw, const float* __restrict__ rbb,
                             const float* __restrict__ rate_b, float* __restrict__ gn, int n)
{
    int f = threadIdx.x;
    float rate = rate_b[0];
    double m   = csum[f] / (double)n;
    double var = csumsq[f] / (double)n - m*m;
    gn[f]       = (float)m;
    gn[64 + f]  = rsqrtf((float)var + 1e-5f);
    gn[128 + f] = nw[f] + (rsw[f]*rate + rsb[f]);
    gn[192 + f] = nb[f] + (rbw[f]*rate + rbb[f]);
}

// gelu(norm(h)) -> xd slice (consumers read strided)
__global__ void gnapply_kernel(const float* __restrict__ h, const float* __restrict__ gn,
                               float* __restrict__ xd, int n)
{
    int idx = blockIdx.x * blockDim.x + threadIdx.x;
    if (idx >= n*32) return;
    int j = idx & 31, r = idx >> 5;
    int f = j*2;
    float2 v = ((const float2*)h)[idx];
    float t0 = (v.x - gn[f])   * gn[64+f]   * gn[128+f]   + gn[192+f];
    float t1 = (v.y - gn[f+1]) * gn[64+f+1] * gn[128+f+1] + gn[192+f+1];
    float2 o = make_float2(gelu_f(t0), gelu_f(t1));
    *(float2*)(xd + (size_t)r*384 + f) = o;
}

// ---------------- fused readout: 8 rows/warp, k-pair FFMA2 packing ----------
// cols per thread: c = lane + 32q (q=0..3). Weights interleaved [kpair][col][2].
#define RO_THREADS 512
#define RO_WARPS   (RO_THREADS/32)
#define RO_ROWS    (RO_WARPS*8)
#define SA_LD 132
#define RO_SMEM ((8192 + 16384 + 7*128 + RO_WARPS*8*SA_LD) * 4)

__global__ __launch_bounds__(RO_THREADS)
void readout_kernel(const float* __restrict__ xf,
                    const float* __restrict__ W1, const float* __restrict__ b1,
                    const float* __restrict__ g1, const float* __restrict__ be1,
                    const float* __restrict__ W2, const float* __restrict__ b2,
                    const float* __restrict__ g2, const float* __restrict__ be2,
                    const float* __restrict__ W3, const float* __restrict__ b3,
                    float* __restrict__ prob, int nrows)
{
    extern __shared__ float sm[];
    float* sW1p = sm;                  // [32 kpair][128 col][2] = 8192
    float* sW2p = sm + 8192;           // [64 kpair][128 col][2] = 16384
    float* sP   = sm + 8192 + 16384;   // b1,g1,be1,b2,g2,be2,W3
    float* sA   = sP + 7*128;          // per-warp activations [RO_WARPS*8][SA_LD]
    int t = threadIdx.x;

    // interleave W1: pair (2kp, 2kp+1) for each col j
    for (int v = t; v < 4096; v += RO_THREADS) {
        int kp = v >> 7, j = v & 127;
        sW1p[v*2]     = W1[(2*kp)*128 + j];
        sW1p[v*2 + 1] = W1[(2*kp+1)*128 + j];
    }
    for (int v = t; v < 8192; v += RO_THREADS) {
        int kp = v >> 7, j = v & 127;
        sW2p[v*2]     = W2[(2*kp)*128 + j];
        sW2p[v*2 + 1] = W2[(2*kp+1)*128 + j];
    }
    if (t < 128) {
        sP[t]       = b1[t];  sP[128 + t] = g1[t];  sP[256 + t] = be1[t];
        sP[384 + t] = b2[t];  sP[512 + t] = g2[t];  sP[640 + t] = be2[t];
        sP[768 + t] = W3[t];
    }

    int lane = t & 31, wp = t >> 5;
    int row0 = blockIdx.x * RO_ROWS + wp * 8;
    float* myA = sA + wp * 8 * SA_LD;

    // stage x (64 per row) into smem
#pragma unroll
    for (int r = 0; r < 8; r++) {
        int gr = min(row0 + r, nrows - 1);
        myA[r*SA_LD + lane]      = xf[(size_t)gr*64 + lane];
        myA[r*SA_LD + 32 + lane] = xf[(size_t)gr*64 + 32 + lane];
    }
    __syncthreads();

    float bias3 = b3[0];
    float bv1[4], bv2[4];
#pragma unroll
    for (int q = 0; q < 4; q++) {
        bv1[q] = sP[lane + 32*q];
        bv2[q] = sP[384 + lane + 32*q];
    }

    // ---- layer 1: 64 -> 128 (32 k-pairs) ----
    unsigned long long acc[8][4];
#pragma unroll
    for (int r = 0; r < 8; r++)
#pragma unroll
        for (int q = 0; q < 4; q++) acc[r][q] = 0ull;

#pragma unroll 4
    for (int kp = 0; kp < 32; kp++) {
        unsigned long long wq[4];
#pragma unroll
        for (int q = 0; q < 4; q++)
            wq[q] = *(const unsigned long long*)(sW1p + kp*256 + (lane + 32*q)*2);
#pragma unroll
        for (int r = 0; r < 8; r++) {
            unsigned long long xr = *(const unsigned long long*)(myA + r*SA_LD + 2*kp);
#pragma unroll
            for (int q = 0; q < 4; q++) ffma2(acc[r][q], xr, wq[q]);
        }
    }

    float A[8][4];
#pragma unroll
    for (int r = 0; r < 8; r++)
#pragma unroll
        for (int q = 0; q < 4; q++) {
            float2 p = unpk(acc[r][q]);
            A[r][q] = p.x + p.y + bv1[q];
        }

    // LN1 + relu -> hidden to smem (cols lane+32q: bank = lane, conflict-free)
    {
        float gg[4], bb[4];
#pragma unroll
        for (int q = 0; q < 4; q++) {
            gg[q] = sP[128 + lane + 32*q];
            bb[q] = sP[256 + lane + 32*q];
        }
        __syncwarp();
#pragma unroll
        for (int r = 0; r < 8; r++) {
            float s  = A[r][0] + A[r][1] + A[r][2] + A[r][3];
            float s2 = A[r][0]*A[r][0] + A[r][1]*A[r][1] + A[r][2]*A[r][2] + A[r][3]*A[r][3];
            for (int o = 16; o; o >>= 1) {
                s  += __shfl_xor_sync(0xffffffffu, s,  o);
                s2 += __shfl_xor_sync(0xffffffffu, s2, o);
            }
            float m   = s  * (1.0f/128.0f);
            float var = s2 * (1.0f/128.0f) - m*m;
            float rs  = rsqrtf(var + 1e-5f);
#pragma unroll
            for (int q = 0; q < 4; q++) {
                float hv = fmaxf((A[r][q] - m)*rs*gg[q] + bb[q], 0.f);
                myA[r*SA_LD + lane + 32*q] = hv;
            }
        }
        __syncwarp();
    }

    // ---- layer 2: 128 -> 128 (64 k-pairs) ----
#pragma unroll
    for (int r = 0; r < 8; r++)
#pragma unroll
        for (int q = 0; q < 4; q++) acc[r][q] = 0ull;

#pragma unroll 4
    for (int kp = 0; kp < 64; kp++) {
        unsigned long long wq[4];
#pragma unroll
        for (int q = 0; q < 4; q++)
            wq[q] = *(const unsigned long long*)(sW2p + kp*256 + (lane + 32*q)*2);
#pragma unroll
        for (int r = 0; r < 8; r++) {
            unsigned long long xr = *(const unsigned long long*)(myA + r*SA_LD + 2*kp);
#pragma unroll
            for (int q = 0; q < 4; q++) ffma2(acc[r][q], xr, wq[q]);
        }
    }

#pragma unroll
    for (int r = 0; r < 8; r++)
#pragma unroll
        for (int q = 0; q < 4; q++) {
            float2 p = unpk(acc[r][q]);
            A[r][q] = p.x + p.y + bv2[q];
        }

    // LN2 + relu + layer3 + sigmoid
    {
        float gg[4], bb[4], w3v[4];
#pragma unroll
        for (int q = 0; q < 4; q++) {
            gg[q]  = sP[512 + lane + 32*q];
            bb[q]  = sP[640 + lane + 32*q];
            w3v[q] = sP[768 + lane + 32*q];
        }
#pragma unroll
        for (int r = 0; r < 8; r++) {
            float s  = A[r][0] + A[r][1] + A[r][2] + A[r][3];
            float s2 = A[r][0]*A[r][0] + A[r][1]*A[r][1] + A[r][2]*A[r][2] + A[r][3]*A[r][3];
            for (int o = 16; o; o >>= 1) {
                s  += __shfl_xor_sync(0xffffffffu, s,  o);
                s2 += __shfl_xor_sync(0xffffffffu, s2, o);
            }
            float m   = s  * (1.0f/128.0f);
            float var = s2 * (1.0f/128.0f) - m*m;
            float rs  = rsqrtf(var + 1e-5f);
            float p = 0.f;
#pragma unroll
            for (int q = 0; q < 4; q++) {
                float v = fmaxf((A[r][q] - m)*rs*gg[q] + bb[q], 0.f);
                p += v * w3v[q];
            }
            for (int o = 16; o; o >>= 1) p += __shfl_xor_sync(0xffffffffu, p, o);
            if (lane == 0 && row0 + r < nrows) prob[row0 + r] = 1.0f / (1.0f + expf(-(p + bias3)));
        }
    }
}

// ---------------- host driver ----------------
extern "C" void kernel_launch(void* const* d_in, const int* in_sizes, int n_in,
                              void* d_out, int out_size)
{
    const float* init_emb    = (const float*)d_in[0];
    const int*   ei          = (const int*)  d_in[1];
    const float* rate_b      = (const float*)d_in[2];
    const float* sage_lin_W  = (const float*)d_in[3];
    const float* sage_lin_b  = (const float*)d_in[4];
    const float* sage_norm_w = (const float*)d_in[5];
    const float* sage_norm_b = (const float*)d_in[6];
    const float* sage_rs_w   = (const float*)d_in[7];
    const float* sage_rs_b   = (const float*)d_in[8];
    const float* sage_rb_w   = (const float*)d_in[9];
    const float* sage_rb_b   = (const float*)d_in[10];
    const float* gin_W1      = (const float*)d_in[11];
    const float* gin_b1      = (const float*)d_in[12];
    const float* gin_W2      = (const float*)d_in[13];
    const float* gin_b2      = (const float*)d_in[14];
    const float* fuse_W      = (const float*)d_in[15];
    const float* fuse_b      = (const float*)d_in[16];
    const float* ro_W1       = (const float*)d_in[17];
    const float* ro_b1       = (const float*)d_in[18];
    const float* ro_ln1_g    = (const float*)d_in[19];
    const float* ro_ln1_b    = (const float*)d_in[20];
    const float* ro_W2       = (const float*)d_in[21];
    const float* ro_b2       = (const float*)d_in[22];
    const float* ro_ln2_g    = (const float*)d_in[23];
    const float* ro_ln2_b    = (const float*)d_in[24];
    const float* ro_W3       = (const float*)d_in[25];
    const float* ro_b3       = (const float*)d_in[26];
    float* out = (float*)d_out;

    float *px, *pxt, *ph, *pxd, *pgn;
    int *pcnt, *pfill, *pstart, *pbsum;
    unsigned* pelist;
    double* pcsum;
    cudaGetSymbolAddress((void**)&px,    g_x);
    cudaGetSymbolAddress((void**)&pxt,   g_xt);
    cudaGetSymbolAddress((void**)&ph,    g_h);
    cudaGetSymbolAddress((void**)&pxd,   g_xd);
    cudaGetSymbolAddress((void**)&pgn,   g_gn);
    cudaGetSymbolAddress((void**)&pcnt,  g_cnt);
    cudaGetSymbolAddress((void**)&pfill, g_fill);
    cudaGetSymbolAddress((void**)&pstart,g_start);
    cudaGetSymbolAddress((void**)&pbsum, g_bsum);
    cudaGetSymbolAddress((void**)&pelist,g_elist);
    cudaGetSymbolAddress((void**)&pcsum, g_csum);

    const int nblk    = (NN + SCAN_BS - 1) / SCAN_BS;
    const int egrid   = (EE + 255) / 256;
    const int ntiles  = (NN + TILE_ROWS - 1) / TILE_ROWS;    // 1563
    const int agrid   = (NN + 7) / 8;                        // 12500
    const int rgrid   = (NN + RO_ROWS - 1) / RO_ROWS;        // 782

    const int smem64   = 3 * CHUNK_F * 4;   // 52KB
    const int smemMlp  = 4 * CHUNK_F * 4;   // 70KB
    const int smemFuse = 8 * CHUNK_F * 4;   // 139KB

    cudaFuncSetAttribute(gemm64_p,    cudaFuncAttributeMaxDynamicSharedMemorySize, smem64);
    cudaFuncSetAttribute(gin_mlp_p,   cudaFuncAttributeMaxDynamicSharedMemorySize, smemMlp);
    cudaFuncSetAttribute(gemm_fuse_p, cudaFuncAttributeMaxDynamicSharedMemorySize, smemFuse);
    cudaFuncSetAttribute(readout_kernel, cudaFuncAttributeMaxDynamicSharedMemorySize, RO_SMEM);

    // ---- CSR build (sage GEMM 0 interleaved at profiling slot 3) ----
    zero_all_kernel<<<(NN + 255)/256, 256>>>(pcnt, pfill, pcsum);
    count_kernel<<<egrid, 256>>>(ei, pcnt);
    scan_block_kernel<<<nblk, SCAN_BS>>>(pcnt, pstart, pbsum, NN);
    gemm64_p<<<P_GRID, 256, smem64>>>(init_emb, 64, sage_lin_W, sage_lin_b,
                                      pxt, NN, ntiles);
    scan_part_kernel<<<1, SCAN_BS>>>(pbsum, nblk);
    scan_add_kernel<<<nblk, SCAN_BS>>>(pstart, pbsum, NN);
    fill_kernel<<<egrid, 256>>>(ei, pstart, pfill, pelist);

    // ---- 3 SAGE+GIN pairs ----
    for (int i = 0; i < 3; i++) {
        const float* xin = (i == 0) ? init_emb : px;
        if (i > 0)
            gemm64_p<<<P_GRID, 256, smem64>>>(xin, 64, sage_lin_W + i*4096,
                                              sage_lin_b + i*64, pxt, NN, ntiles);
        sage_agg_kernel<<<agrid, 256>>>(pxt, xin, pstart, pcnt, pelist, ph, NN);
        colsum_kernel<<<444, 256>>>(ph, pcsum + i*128, pcsum + i*128 + 64, NN);
        gnfin_kernel<<<1, 64>>>(pcsum + i*128, pcsum + i*128 + 64,
                                sage_norm_w + i*64, sage_norm_b + i*64,
                                sage_rs_w + i*64, sage_rs_b + i*64,
                                sage_rb_w + i*64, sage_rb_b + i*64,
                                rate_b, pgn, NN);
        gnapply_kernel<<<(NN*32 + 255)/256, 256>>>(ph, pgn, pxd + (size_t)(2*i)*64, NN);
        gin_agg_kernel<<<agrid, 256>>>(pxd + (size_t)(2*i)*64, 96,
                                       pstart, pcnt, pelist, pxt, NN);
        gin_mlp_p<<<P_GRID, 256, smemMlp>>>(pxt, gin_W1 + i*4096, gin_b1 + i*64,
                                            gin_W2 + i*4096, gin_b2 + i*64,
                                            px, pxd + (size_t)(2*i+1)*64, NN, ntiles);
    }

    // ---- fuse: x_final = x_dense @ fuse_W + fuse_b ----
    gemm_fuse_p<<<148, 256, smemFuse>>>(pxd, fuse_W, fuse_b, out, NN, ntiles);

    // ---- fused readout -> prob ----
    readout_kernel<<<rgrid, RO_THREADS, RO_SMEM>>>(
        out, ro_W1, ro_b1, ro_ln1_g, ro_ln1_b,
        ro_W2, ro_b2, ro_ln2_g, ro_ln2_b,
        ro_W3, ro_b3, out + (size_t)(out_size - NN), NN);
}